// round 1
// baseline (speedup 1.0000x reference)
#include <cuda_runtime.h>
#include <cuda_bf16.h>

// Problem constants (match reference)
#define N_NODES 50000
#define N_EDGES 800000
#define D_IN    128
#define D_HID   128
#define D_OUT   64

// -------- device scratch (allocation-free rule: __device__ globals) --------
__device__ float g_support[N_NODES * D_HID];   // GEMM output / spmm input
__device__ float g_h[N_NODES * D_HID];         // hidden activations
__device__ int   g_row_ptr[N_NODES + 1];
__device__ int   g_counts[N_NODES];
__device__ int   g_cursor[N_NODES];
__device__ int   g_cols[N_EDGES];
__device__ float g_vals[N_EDGES];

// ============================ CSR construction ==============================

__global__ void zero_kernel() {
    int i = blockIdx.x * blockDim.x + threadIdx.x;
    if (i < N_NODES) { g_counts[i] = 0; g_cursor[i] = 0; }
}

__global__ void hist_kernel(const int* __restrict__ edge_row) {
    int e = blockIdx.x * blockDim.x + threadIdx.x;
    if (e < N_EDGES) atomicAdd(&g_counts[edge_row[e]], 1);
}

// single-block exclusive scan of g_counts -> g_row_ptr
__global__ void scan_kernel() {
    __shared__ int warp_sums[32];
    __shared__ int carry_s;
    const int tid  = threadIdx.x;
    const int lane = tid & 31;
    const int wid  = tid >> 5;
    if (tid == 0) carry_s = 0;
    __syncthreads();
    for (int base = 0; base < N_NODES; base += 1024) {
        int i = base + tid;
        int v = (i < N_NODES) ? g_counts[i] : 0;
        // warp inclusive scan
        int incl = v;
        #pragma unroll
        for (int off = 1; off < 32; off <<= 1) {
            int t = __shfl_up_sync(0xffffffffu, incl, off);
            if (lane >= off) incl += t;
        }
        if (lane == 31) warp_sums[wid] = incl;
        __syncthreads();
        if (wid == 0) {
            int ws = warp_sums[lane];
            int wincl = ws;
            #pragma unroll
            for (int off = 1; off < 32; off <<= 1) {
                int t = __shfl_up_sync(0xffffffffu, wincl, off);
                if (lane >= off) wincl += t;
            }
            warp_sums[lane] = wincl - ws;   // exclusive warp prefix
        }
        __syncthreads();
        int carry = carry_s;
        int excl = carry + warp_sums[wid] + incl - v;
        if (i < N_NODES) g_row_ptr[i] = excl;
        __syncthreads();
        if (tid == 1023) carry_s = carry + warp_sums[31] + incl;  // block total + carry
        __syncthreads();
    }
    if (tid == 0) g_row_ptr[N_NODES] = carry_s;
}

__global__ void scatter_kernel(const int* __restrict__ edge_row,
                               const int* __restrict__ edge_col,
                               const float* __restrict__ edge_val) {
    int e = blockIdx.x * blockDim.x + threadIdx.x;
    if (e < N_EDGES) {
        int r = edge_row[e];
        int p = g_row_ptr[r] + atomicAdd(&g_cursor[r], 1);
        g_cols[p] = edge_col[e];
        g_vals[p] = edge_val[e];
    }
}

// ================================ GEMM ======================================
// C[N, NC] = A[N, 128] @ W[128, NC], fp32, K split into two 64-chunks so the
// static smem stays at <= 48KB. Thread computes an 8x4 micro-tile.

template <int NC>
__global__ void gemm_kernel(const float* __restrict__ A,
                            const float* __restrict__ W,
                            float* __restrict__ C, int N) {
    constexpr int K   = 128;
    constexpr int KC  = 64;           // K chunk
    constexpr int TM  = 64;           // rows per block
    constexpr int CPT = 4;            // cols per thread
    constexpr int RPT = 8;            // rows per thread
    constexpr int TC  = NC / CPT;     // threads along N (32 or 16)
    constexpr int NT  = TC * (TM / RPT);  // 256 or 128 threads

    __shared__ float W_s[KC][NC];     // 32KB or 16KB
    __shared__ float A_s[TM][KC];     // 16KB

    const int tid  = threadIdx.x;
    const int cid  = tid % TC;
    const int rgrp = tid / TC;        // 0..7
    const int row0 = blockIdx.x * TM;

    float acc[RPT][CPT];
    #pragma unroll
    for (int r = 0; r < RPT; r++)
        #pragma unroll
        for (int c = 0; c < CPT; c++) acc[r][c] = 0.0f;

    for (int kc = 0; kc < K; kc += KC) {
        // load W chunk: KC * NC floats
        for (int i = tid * 4; i < KC * NC; i += NT * 4) {
            int ks = i / NC, c = i % NC;
            *(float4*)&W_s[ks][c] = *(const float4*)&W[(kc + ks) * NC + c];
        }
        // load A chunk: TM * KC floats
        for (int i = tid * 4; i < TM * KC; i += NT * 4) {
            int r = i / KC, kk = i % KC;
            int gr = row0 + r;
            float4 v = make_float4(0.f, 0.f, 0.f, 0.f);
            if (gr < N) v = *(const float4*)&A[(size_t)gr * K + kc + kk];
            *(float4*)&A_s[r][kk] = v;
        }
        __syncthreads();

        #pragma unroll 8
        for (int k = 0; k < KC; k++) {
            float4 w = *(const float4*)&W_s[k][cid * CPT];
            #pragma unroll
            for (int r = 0; r < RPT; r++) {
                float a = A_s[rgrp * RPT + r][k];
                acc[r][0] += a * w.x;
                acc[r][1] += a * w.y;
                acc[r][2] += a * w.z;
                acc[r][3] += a * w.w;
            }
        }
        __syncthreads();
    }

    #pragma unroll
    for (int r = 0; r < RPT; r++) {
        int gr = row0 + rgrp * RPT + r;
        if (gr < N)
            *(float4*)&C[(size_t)gr * NC + cid * CPT] = *(float4*)&acc[r][0];
    }
}

// ================================ SpMM ======================================
// warp-per-row segmented sum over CSR, fused bias (+ ReLU). No atomics.

template <int D, bool RELU>
__global__ void spmm_kernel(const float* __restrict__ S,
                            const float* __restrict__ bias,
                            float* __restrict__ out, int N) {
    constexpr int F = D / 32;   // floats per lane (4 or 2)
    const int warp = (blockIdx.x * blockDim.x + threadIdx.x) >> 5;
    const int lane = threadIdx.x & 31;
    if (warp >= N) return;

    const int start = g_row_ptr[warp];
    const int end   = g_row_ptr[warp + 1];

    float acc[F];
    #pragma unroll
    for (int j = 0; j < F; j++) acc[j] = 0.0f;

    #pragma unroll 4
    for (int e = start; e < end; e++) {
        int   c = __ldg(&g_cols[e]);
        float v = __ldg(&g_vals[e]);
        if (F == 4) {
            float4 s = *(const float4*)&S[(size_t)c * D + lane * 4];
            acc[0] += v * s.x; acc[1] += v * s.y;
            acc[2] += v * s.z; acc[3] += v * s.w;
        } else {
            float2 s = *(const float2*)&S[(size_t)c * D + lane * 2];
            acc[0] += v * s.x; acc[1] += v * s.y;
        }
    }

    #pragma unroll
    for (int j = 0; j < F; j++) {
        float r = acc[j] + __ldg(&bias[lane * F + j]);
        if (RELU) r = fmaxf(r, 0.0f);
        acc[j] = r;
    }
    if (F == 4)
        *(float4*)&out[(size_t)warp * D + lane * 4] = make_float4(acc[0], acc[1], acc[2], acc[3]);
    else
        *(float2*)&out[(size_t)warp * D + lane * 2] = make_float2(acc[0], acc[1]);
}

// ============================== launch =====================================

extern "C" void kernel_launch(void* const* d_in, const int* in_sizes, int n_in,
                              void* d_out, int out_size) {
    const float* x        = (const float*)d_in[0];
    const int*   edge_row = (const int*)  d_in[1];
    const int*   edge_col = (const int*)  d_in[2];
    const float* edge_val = (const float*)d_in[3];
    const float* W1       = (const float*)d_in[4];
    const float* b1       = (const float*)d_in[5];
    const float* W2       = (const float*)d_in[6];
    const float* b2       = (const float*)d_in[7];
    const float* W3       = (const float*)d_in[8];
    const float* b3       = (const float*)d_in[9];
    float* out = (float*)d_out;

    const int N = N_NODES;
    const int E = N_EDGES;

    // ---- CSR build (once per launch) ----
    zero_kernel<<<(N + 255) / 256, 256>>>();
    hist_kernel<<<(E + 255) / 256, 256>>>(edge_row);
    scan_kernel<<<1, 1024>>>();
    scatter_kernel<<<(E + 255) / 256, 256>>>(edge_row, edge_col, edge_val);

    // symbol addresses for scratch buffers used as kernel args
    float* support; cudaGetSymbolAddress((void**)&support, g_support);
    float* h;       cudaGetSymbolAddress((void**)&h, g_h);

    const int gemm_grid = (N + 63) / 64;
    const int spmm_grid = (N + 7) / 8;   // 8 warps per 256-thread block

    // ---- layer 1 ----
    gemm_kernel<128><<<gemm_grid, 256>>>(x, W1, support, N);
    spmm_kernel<128, true><<<spmm_grid, 256>>>(support, b1, h, N);
    // ---- layer 2 ----
    gemm_kernel<128><<<gemm_grid, 256>>>(h, W2, support, N);
    spmm_kernel<128, true><<<spmm_grid, 256>>>(support, b2, h, N);
    // ---- layer 3 ----
    gemm_kernel<64><<<gemm_grid, 128>>>(h, W3, support, N);
    spmm_kernel<64, false><<<spmm_grid, 256>>>(support, b3, out, N);
}